// round 9
// baseline (speedup 1.0000x reference)
#include <cuda_runtime.h>
#include <cstdint>

// ============================================================================
// relu(x @ W^T + b):  B=131072, D_IN=D_OUT=256, fp32 in/out.
//
// mma.sync m16n8k8 tf32, cvt.rna operands (unbiased, rel_err ~2.8e-4).
//
// R8 vs R7 (124.9us, latency-bound: tensor 46%, issue 26%, occ=1 CTA/SM):
//  - CTA tile 128x128, 4 warps (2x2, warp tile 64x64), 128 threads.
//    ~190 regs/thread + 74KB smem -> TWO CTAs per SM: independent barriers,
//    prologue/epilogue of one CTA overlaps compute of the other.
//  - cp.async.cg global->shared (raw fp32): no LDG->reg->STS round trip, no
//    prefetch register buffers. cvt.rna applied to fragments after LDS.
//  - 2-stage ring, pitch-36 padded smem (conflict-free frag LDS, 16B-aligned
//    cp.async dst). Grid (2 n-blocks fastest) so x-sharing siblings co-run.
// ============================================================================

#define DEVINL static __device__ __forceinline__

static constexpr int DIM     = 256;
static constexpr int TILE_M  = 128;
static constexpr int TILE_N  = 128;
static constexpr int NCH     = 8;            // K chunks of 32
static constexpr int PITCH   = 36;           // floats per row-chunk (144B, 16B-mult)
static constexpr int THREADS = 128;

static constexpr int A_WORDS     = TILE_M * PITCH;       // 4608
static constexpr int B_WORDS     = TILE_N * PITCH;       // 4608
static constexpr int STAGE_WORDS = A_WORDS + B_WORDS;    // 9216
static constexpr int BIAS_WORDS  = 128;
static constexpr int SMEM_BYTES  = (BIAS_WORDS + 2 * STAGE_WORDS) * 4; // 74240

DEVINL uint32_t smem_u32(const void* p) {
    uint32_t a;
    asm("{ .reg .u64 t; cvta.to.shared.u64 t, %1; cvt.u32.u64 %0, t; }"
        : "=r"(a) : "l"(p));
    return a;
}
DEVINL uint32_t f2tf(float f) {
    uint32_t r;
    asm("cvt.rna.tf32.f32 %0, %1;" : "=r"(r) : "f"(f));
    return r;
}
DEVINL void cp16(uint32_t saddr, const void* gaddr) {
    asm volatile("cp.async.cg.shared.global [%0], [%1], 16;"
                 :: "r"(saddr), "l"(gaddr) : "memory");
}
#define CP_COMMIT()  asm volatile("cp.async.commit_group;" ::: "memory")
#define CP_WAIT(n)   asm volatile("cp.async.wait_group %0;" :: "n"(n) : "memory")

DEVINL void mma_tf32(float* d, const uint32_t* a, const uint32_t* b) {
    asm volatile(
        "mma.sync.aligned.m16n8k8.row.col.f32.tf32.tf32.f32 "
        "{%0,%1,%2,%3}, {%4,%5,%6,%7}, {%8,%9}, {%0,%1,%2,%3};"
        : "+f"(d[0]), "+f"(d[1]), "+f"(d[2]), "+f"(d[3])
        : "r"(a[0]), "r"(a[1]), "r"(a[2]), "r"(a[3]),
          "r"(b[0]), "r"(b[1]));
}

__global__ void __launch_bounds__(THREADS, 2)
gemm_bias_relu_cp(const float4* __restrict__ x4,
                  const float4* __restrict__ w4,
                  const float*  __restrict__ bias,
                  float2*       __restrict__ out2) {
    extern __shared__ float smf[];
    float* bsm = smf;
    float* stgf[2] = { smf + BIAS_WORDS, smf + BIAS_WORDS + STAGE_WORDS };
    const uint32_t sb = smem_u32(smf);
    const uint32_t stgu[2] = { sb + BIAS_WORDS * 4,
                               sb + (BIAS_WORDS + STAGE_WORDS) * 4 };

    const int tid = threadIdx.x;
    const int nblk = blockIdx.x;                    // 0..1 (fastest: siblings share x via L2)
    const long m_base = (long)blockIdx.y * TILE_M;
    const int  n_base = nblk * TILE_N;

    bsm[tid] = bias[n_base + tid];

    // -------- loader mapping: thread owns rows {lr+16i, i=0..7}, 16B seg --------
    const int lr  = tid >> 3;    // 0..15
    const int seg = tid & 7;     // 0..7

    uint32_t soff[8];            // byte offset within a stage (same for A and B rows)
#pragma unroll
    for (int i = 0; i < 8; i++)
        soff[i] = (uint32_t)(((lr + 16 * i) * PITCH + seg * 4) * 4);

    const float4* xa = x4 + (m_base + lr) * 64 + seg;       // x row pitch = 64 float4
    const float4* wb = w4 + ((long)n_base + lr) * 64 + seg; // W row pitch = 64 float4

    auto cp_chunk = [&](int c, uint32_t stage) {
        const long o = (long)c * 8;
#pragma unroll
        for (int i = 0; i < 8; i++)
            cp16(stage + soff[i], xa + (long)i * 1024 + o);           // 16 rows apart
#pragma unroll
        for (int i = 0; i < 8; i++)
            cp16(stage + A_WORDS * 4 + soff[i], wb + (long)i * 1024 + o);
    };

    // -------- compute mapping: 4 warps, 2(M) x 2(N), warp tile 64x64 --------
    const int wid = tid >> 5, l = tid & 31;
    const int mw = wid >> 1, nw = wid & 1;
    const int qr = l >> 2, ql = l & 3;

    int aoff[4], boff[8];
#pragma unroll
    for (int mi = 0; mi < 4; mi++)
        aoff[mi] = (mw * 64 + mi * 16 + qr) * PITCH + ql;
#pragma unroll
    for (int ni = 0; ni < 8; ni++)
        boff[ni] = A_WORDS + (nw * 64 + ni * 8 + qr) * PITCH + ql;

    float acc[4][8][4];
#pragma unroll
    for (int mi = 0; mi < 4; mi++)
#pragma unroll
        for (int ni = 0; ni < 8; ni++)
#pragma unroll
            for (int r = 0; r < 4; r++) acc[mi][ni][r] = 0.0f;

    auto compute_chunk = [&](const float* s) {
#pragma unroll
        for (int ks = 0; ks < 4; ks++) {
            uint32_t a[4][4], b[8][2];
#pragma unroll
            for (int mi = 0; mi < 4; mi++) {
                const int ba = aoff[mi] + ks * 8;
                a[mi][0] = f2tf(s[ba]);
                a[mi][1] = f2tf(s[ba + 8 * PITCH]);
                a[mi][2] = f2tf(s[ba + 4]);
                a[mi][3] = f2tf(s[ba + 8 * PITCH + 4]);
            }
#pragma unroll
            for (int ni = 0; ni < 8; ni++) {
                const int bb = boff[ni] + ks * 8;
                b[ni][0] = f2tf(s[bb]);
                b[ni][1] = f2tf(s[bb + 4]);
            }
#pragma unroll
            for (int mi = 0; mi < 4; mi++)
#pragma unroll
                for (int ni = 0; ni < 8; ni++)
                    mma_tf32(acc[mi][ni], a[mi], b[ni]);
        }
    };

    // -------- pipeline: 2-stage cp.async ring --------
    cp_chunk(0, stgu[0]); CP_COMMIT();
    cp_chunk(1, stgu[1]); CP_COMMIT();
    CP_WAIT(1);                       // chunk 0 landed
    __syncthreads();

#pragma unroll 1
    for (int c = 0; c < NCH; c++) {
        const int s = c & 1;
        compute_chunk(stgf[s]);
        __syncthreads();              // all warps done reading stage s
        if (c < NCH - 2) {
            cp_chunk(c + 2, stgu[s]); CP_COMMIT();
            CP_WAIT(1);               // chunk c+1 landed
            __syncthreads();
        } else if (c == NCH - 2) {
            CP_WAIT(0);               // last chunk landed
            __syncthreads();
        }
    }

    // -------- epilogue: bias + relu, float2 stores --------
#pragma unroll
    for (int mi = 0; mi < 4; mi++) {
        const long r0 = m_base + mw * 64 + mi * 16 + qr;
#pragma unroll
        for (int ni = 0; ni < 8; ni++) {
            const int col = nw * 64 + ni * 8 + ql * 2;    // local column
            const float b0 = bsm[col], b1 = bsm[col + 1];
            float2 v0, v1;
            v0.x = fmaxf(acc[mi][ni][0] + b0, 0.0f);
            v0.y = fmaxf(acc[mi][ni][1] + b1, 0.0f);
            v1.x = fmaxf(acc[mi][ni][2] + b0, 0.0f);
            v1.y = fmaxf(acc[mi][ni][3] + b1, 0.0f);
            const int gc2 = (n_base + col) >> 1;          // float2 column index
            out2[r0 * 128 + gc2]       = v0;
            out2[(r0 + 8) * 128 + gc2] = v1;
        }
    }
}

extern "C" void kernel_launch(void* const* d_in, const int* in_sizes, int n_in,
                              void* d_out, int out_size) {
    const float* x = (const float*)d_in[0];   // [B, 256]
    const float* W = (const float*)d_in[1];   // [256, 256]
    const float* b = (const float*)d_in[2];   // [256]

    const int rows = in_sizes[0] / DIM;       // 131072
    dim3 grid(DIM / TILE_N, rows / TILE_M);   // (2, 1024): n fastest -> x shared in L2

    cudaFuncSetAttribute(gemm_bias_relu_cp,
                         cudaFuncAttributeMaxDynamicSharedMemorySize, SMEM_BYTES);
    gemm_bias_relu_cp<<<grid, THREADS, SMEM_BYTES>>>(
        (const float4*)x, (const float4*)W, b, (float2*)d_out);
}

// round 10
// speedup vs baseline: 1.3850x; 1.3850x over previous
#include <cuda_runtime.h>
#include <cuda_fp16.h>
#include <cstdint>

// ============================================================================
// relu(x @ W^T + b):  B=131072, D_IN=D_OUT=256, fp32 in/out.
//
// R9: legacy tf32 mma path measured saturated at ~140-150 TF/s (tensor% pinned
// ~46% across R6/R7/R8 regardless of config). Switch to m16n8k16 fp16 HMMA
// (2x rate, ~300 TF/s). fp16 mantissa (11 bits) == tf32 mantissa -> identical
// unbiased rounding error: rel_err ~2.8e-4 (measured on tf32 path). Operand
// ranges (x~N(0,1), W in +-1/16) are safely inside fp16 range.
//
// Skeleton = R6 (best measured): 512 thr / 16 warps, CTA 128x256, warp 64x32,
// 2-stage smem ring + one-chunk-ahead register prefetch. fp16 stages at pitch
// 40 halfs (80B): fragment LDS.32 perfectly bank-conflict-free; loader row
// permutation (bit0<->bit2) makes STS.128 phases conflict-free too.
// ============================================================================

#define DEVINL static __device__ __forceinline__

static constexpr int DIM     = 256;
static constexpr int TILE_M  = 128;
static constexpr int NCH     = 8;                  // K chunks of 32
static constexpr int THREADS = 512;
static constexpr int PITCH_H = 40;                 // halfs per row-chunk (80 B)

static constexpr int A_HALFS     = TILE_M * PITCH_H;      // 5120
static constexpr int B_HALFS     = DIM * PITCH_H;         // 10240
static constexpr int STAGE_HALFS = A_HALFS + B_HALFS;     // 15360
static constexpr int BIAS_WORDS  = 256;
static constexpr int SMEM_BYTES  = BIAS_WORDS * 4 + 2 * STAGE_HALFS * 2; // 62464

DEVINL uint32_t pack_h2(float lo, float hi) {       // -> f16x2 {lo, hi}
    uint32_t r;
    asm("cvt.rn.f16x2.f32 %0, %1, %2;" : "=r"(r) : "f"(hi), "f"(lo));
    return r;
}

DEVINL void mma_f16(float* d, const uint32_t* a, const uint32_t* b) {
    asm volatile(
        "mma.sync.aligned.m16n8k16.row.col.f32.f16.f16.f32 "
        "{%0,%1,%2,%3}, {%4,%5,%6,%7}, {%8,%9}, {%0,%1,%2,%3};"
        : "+f"(d[0]), "+f"(d[1]), "+f"(d[2]), "+f"(d[3])
        : "r"(a[0]), "r"(a[1]), "r"(a[2]), "r"(a[3]),
          "r"(b[0]), "r"(b[1]));
}

__global__ void __launch_bounds__(THREADS, 1)
gemm_bias_relu_f16(const float4* __restrict__ x4,
                   const float4* __restrict__ w4,
                   const float*  __restrict__ bias,
                   float2*       __restrict__ out2) {
    extern __shared__ float smf[];
    float*    bsm = smf;
    __half*   hb  = (__half*)(smf + BIAS_WORDS);
    __half*   stg[2] = { hb, hb + STAGE_HALFS };

    const int  tid    = threadIdx.x;
    const long m_base = (long)blockIdx.x * TILE_M;

    if (tid < 256) bsm[tid] = bias[tid];

    // ---------------- loader mapping ----------------
    // vq = tid>>2 selects a row via bit0<->bit2 swap so each 8-lane STS.128
    // phase covers rows r and r+4 (pitch 20 words: bank offsets differ by 16
    // -> conflict-free). seg = 16B segment (8 halfs = K-span 8).
    const int vq  = tid >> 2;                         // 0..127
    const int seg = tid & 3;                          // 0..3
    const int rowA = (vq & ~7) | ((vq & 1) << 2) | ((vq >> 1) & 3);

    const long gaA  = (m_base + rowA) * 64 + seg * 2;          // float4 units
    const long gaB0 = (long)rowA * 64 + seg * 2;               // W row rowA
    const long gaB1 = (long)(rowA + 128) * 64 + seg * 2;       // W row rowA+128

    __half* sA  = /*filled per stage*/ nullptr; (void)sA;
    const int soA  = rowA * PITCH_H + seg * 8;                         // half idx
    const int soB0 = A_HALFS + rowA * PITCH_H + seg * 8;
    const int soB1 = A_HALFS + (rowA + 128) * PITCH_H + seg * 8;

    float4 ra[2], rb0[2], rb1[2];

    auto ldg_chunk = [&](int c) {
        const long o = (long)c * 8;
        ra[0]  = x4[gaA + o];      ra[1]  = x4[gaA + o + 1];
        rb0[0] = w4[gaB0 + o];     rb0[1] = w4[gaB0 + o + 1];
        rb1[0] = w4[gaB1 + o];     rb1[1] = w4[gaB1 + o + 1];
    };

    auto pack16 = [](const float4* v) {
        uint4 u;
        u.x = pack_h2(v[0].x, v[0].y);
        u.y = pack_h2(v[0].z, v[0].w);
        u.z = pack_h2(v[1].x, v[1].y);
        u.w = pack_h2(v[1].z, v[1].w);
        return u;
    };

    auto sts_chunk = [&](__half* s) {
        *(uint4*)(s + soA)  = pack16(ra);
        *(uint4*)(s + soB0) = pack16(rb0);
        *(uint4*)(s + soB1) = pack16(rb1);
    };

    // ---------------- compute mapping: 16 warps, 2(M) x 8(N) ----------------
    const int wid = tid >> 5, l = tid & 31;
    const int mw = wid >> 3, nw = wid & 7;
    const int qr = l >> 2, ql = l & 3;

    int aoff[4], boff[4];
#pragma unroll
    for (int mi = 0; mi < 4; mi++)
        aoff[mi] = (mw * 64 + mi * 16 + qr) * PITCH_H + 2 * ql;
#pragma unroll
    for (int ni = 0; ni < 4; ni++)
        boff[ni] = A_HALFS + (nw * 32 + ni * 8 + qr) * PITCH_H + 2 * ql;

    float acc[4][4][4];
#pragma unroll
    for (int mi = 0; mi < 4; mi++)
#pragma unroll
        for (int ni = 0; ni < 4; ni++)
#pragma unroll
            for (int r = 0; r < 4; r++) acc[mi][ni][r] = 0.0f;

    auto ld32 = [](const __half* p) { return *(const uint32_t*)p; };

    auto compute_chunk = [&](const __half* s) {
#pragma unroll
        for (int ks = 0; ks < 2; ks++) {           // K=16 per mma
            const int ko = ks * 16;
            uint32_t a[4][4], b[4][2];
#pragma unroll
            for (int mi = 0; mi < 4; mi++) {
                const __half* p = s + aoff[mi] + ko;
                a[mi][0] = ld32(p);
                a[mi][1] = ld32(p + 8 * PITCH_H);
                a[mi][2] = ld32(p + 8);
                a[mi][3] = ld32(p + 8 * PITCH_H + 8);
            }
#pragma unroll
            for (int ni = 0; ni < 4; ni++) {
                const __half* p = s + boff[ni] + ko;
                b[ni][0] = ld32(p);
                b[ni][1] = ld32(p + 8);
            }
#pragma unroll
            for (int mi = 0; mi < 4; mi++)
#pragma unroll
                for (int ni = 0; ni < 4; ni++)
                    mma_f16(acc[mi][ni], a[mi], b[ni]);
        }
    };

    // ---------------- pipeline (R6 skeleton) ----------------
    ldg_chunk(0);
    sts_chunk(stg[0]);
    ldg_chunk(1);
    __syncthreads();

#pragma unroll 1
    for (int c = 0; c < NCH; c++) {
        compute_chunk(stg[c & 1]);
        if (c < NCH - 1) {
            sts_chunk(stg[(c + 1) & 1]);           // regs hold chunk c+1
            if (c < NCH - 2) ldg_chunk(c + 2);     // hidden by compute(c+1)
        }
        __syncthreads();
    }

    // ---------------- epilogue: bias + relu, float2 stores ----------------
#pragma unroll
    for (int mi = 0; mi < 4; mi++) {
        const long r0 = m_base + mw * 64 + mi * 16 + qr;
#pragma unroll
        for (int ni = 0; ni < 4; ni++) {
            const int col = nw * 32 + ni * 8 + ql * 2;
            const float b0 = bsm[col], b1 = bsm[col + 1];
            float2 v0, v1;
            v0.x = fmaxf(acc[mi][ni][0] + b0, 0.0f);
            v0.y = fmaxf(acc[mi][ni][1] + b1, 0.0f);
            v1.x = fmaxf(acc[mi][ni][2] + b0, 0.0f);
            v1.y = fmaxf(acc[mi][ni][3] + b1, 0.0f);
            out2[r0 * 128 + (col >> 1)]       = v0;
            out2[(r0 + 8) * 128 + (col >> 1)] = v1;
        }
    }
}

extern "C" void kernel_launch(void* const* d_in, const int* in_sizes, int n_in,
                              void* d_out, int out_size) {
    const float* x = (const float*)d_in[0];   // [B, 256]
    const float* W = (const float*)d_in[1];   // [256, 256]
    const float* b = (const float*)d_in[2];   // [256]

    const int rows = in_sizes[0] / DIM;       // 131072
    const int grid = rows / TILE_M;           // 1024

    cudaFuncSetAttribute(gemm_bias_relu_f16,
                         cudaFuncAttributeMaxDynamicSharedMemorySize, SMEM_BYTES);
    gemm_bias_relu_f16<<<grid, THREADS, SMEM_BYTES>>>(
        (const float4*)x, (const float4*)W, b, (float2*)d_out);
}

// round 12
// speedup vs baseline: 1.4258x; 1.0294x over previous
#include <cuda_runtime.h>
#include <cuda_fp16.h>
#include <cstdint>

// ============================================================================
// relu(x @ W^T + b):  B=131072, D_IN=D_OUT=256, fp32 in/out.
//
// R11 vs R10 (104us): fp16 fragment LDS had inherent 2-way bank conflicts
// (ql stride = 8B => even banks only under any 16B-multiple pitch). Fix with
// XOR word swizzle: row r, logical word w stored at w ^ (((r>>1)&3)<<2).
//  - fragment LDS.32: banks (qr&1)*16 + ql + 4*(u^((qr>>1)&3)) -> all distinct
//  - STS.128: 16B stays contiguous (XOR is a multiple of 4 words); an 8-lane
//    phase = 2 rows x 4 segs = banks 0..31 exactly.
//  - no padding: 64B rows, stage 24KB (was 30KB).
// Skeleton unchanged from R10: 512 thr / 16 warps, CTA 128x256, warp 64x32,
// m16n8k16 fp16 HMMA (fp32 accum), 2-stage ring + reg prefetch.
// ============================================================================

#define DEVINL static __device__ __forceinline__

static constexpr int DIM     = 256;
static constexpr int TILE_M  = 128;
static constexpr int NCH     = 8;                  // K chunks of 32
static constexpr int THREADS = 512;
static constexpr int ROW_H   = 32;                 // halfs per row-chunk (64 B)

static constexpr int A_HALFS     = TILE_M * ROW_H;        // 4096
static constexpr int B_HALFS     = DIM * ROW_H;           // 8192
static constexpr int STAGE_HALFS = A_HALFS + B_HALFS;     // 12288 (24 KB)
static constexpr int BIAS_WORDS  = 256;
static constexpr int SMEM_BYTES  = BIAS_WORDS * 4 + 2 * STAGE_HALFS * 2; // 50176

DEVINL uint32_t pack_h2(float lo, float hi) {       // f16x2 {lo | hi<<16}
    uint32_t r;
    asm("cvt.rn.f16x2.f32 %0, %1, %2;" : "=r"(r) : "f"(hi), "f"(lo));
    return r;
}

DEVINL void mma_f16(float* d, const uint32_t* a, const uint32_t* b) {
    asm volatile(
        "mma.sync.aligned.m16n8k16.row.col.f32.f16.f16.f32 "
        "{%0,%1,%2,%3}, {%4,%5,%6,%7}, {%8,%9}, {%0,%1,%2,%3};"
        : "+f"(d[0]), "+f"(d[1]), "+f"(d[2]), "+f"(d[3])
        : "r"(a[0]), "r"(a[1]), "r"(a[2]), "r"(a[3]),
          "r"(b[0]), "r"(b[1]));
}

__global__ void __launch_bounds__(THREADS, 1)
gemm_bias_relu_f16(const float4* __restrict__ x4,
                   const float4* __restrict__ w4,
                   const float*  __restrict__ bias,
                   float2*       __restrict__ out2) {
    extern __shared__ float smf[];
    float*  bsm = smf;
    __half* hb  = (__half*)(smf + BIAS_WORDS);
    __half* stg[2] = { hb, hb + STAGE_HALFS };

    const int  tid    = threadIdx.x;
    const long m_base = (long)blockIdx.x * TILE_M;

    if (tid < 256) bsm[tid] = bias[tid];

    // ---------------- loader mapping ----------------
    // Thread owns: A row `row`, W rows {row, row+128}; 16B segment s (8 k's).
    // Physical word of 16B unit: (4s) ^ (((row>>1)&3)<<2) = 4*(s ^ xqr).
    const int row = tid >> 2;                      // 0..127
    const int s   = tid & 3;                       // 0..3
    const int sw  = s ^ ((row >> 1) & 3);          // swizzled 16B slot

    const int soA  = row * ROW_H + 8 * sw;                     // half index
    const int soB0 = A_HALFS + row * ROW_H + 8 * sw;           // ((row+128)>>1)&3
    const int soB1 = A_HALFS + (row + 128) * ROW_H + 8 * sw;   //  == (row>>1)&3

    const long gaA  = (m_base + row) * 64 + s * 2;             // float4 units
    const long gaB0 = (long)row * 64 + s * 2;
    const long gaB1 = (long)(row + 128) * 64 + s * 2;

    float4 ra[2], rb0[2], rb1[2];

    auto ldg_chunk = [&](int c) {
        const long o = (long)c * 8;
        ra[0]  = x4[gaA + o];    ra[1]  = x4[gaA + o + 1];
        rb0[0] = w4[gaB0 + o];   rb0[1] = w4[gaB0 + o + 1];
        rb1[0] = w4[gaB1 + o];   rb1[1] = w4[gaB1 + o + 1];
    };

    auto pack16 = [](const float4* v) {
        uint4 u;
        u.x = pack_h2(v[0].x, v[0].y);
        u.y = pack_h2(v[0].z, v[0].w);
        u.z = pack_h2(v[1].x, v[1].y);
        u.w = pack_h2(v[1].z, v[1].w);
        return u;
    };

    auto sts_chunk = [&](__half* st) {
        *(uint4*)(st + soA)  = pack16(ra);
        *(uint4*)(st + soB0) = pack16(rb0);
        *(uint4*)(st + soB1) = pack16(rb1);
    };

    // ---------------- compute mapping: 16 warps, 2(M) x 8(N) ----------------
    const int wid = tid >> 5, l = tid & 31;
    const int mw = wid >> 3, nw = wid & 7;
    const int qr = l >> 2, ql = l & 3;
    const int xq = (qr >> 1) & 3;

    // Per-lane swizzled half-offset within a row for fragment group u=0..3
    // (u = 2*ks + {0:k, 1:k+8}); logical word = ql + 4u -> phys = ql + 4*(u^xq).
    int woff[4];
#pragma unroll
    for (int u = 0; u < 4; u++) woff[u] = (ql + 4 * (u ^ xq)) * 2;

    int arow[4], brow[4];                           // half base of fragment rows
#pragma unroll
    for (int mi = 0; mi < 4; mi++)
        arow[mi] = (mw * 64 + mi * 16 + qr) * ROW_H;
#pragma unroll
    for (int ni = 0; ni < 4; ni++)
        brow[ni] = A_HALFS + (nw * 32 + ni * 8 + qr) * ROW_H;

    float acc[4][4][4];
#pragma unroll
    for (int mi = 0; mi < 4; mi++)
#pragma unroll
        for (int ni = 0; ni < 4; ni++)
#pragma unroll
            for (int r = 0; r < 4; r++) acc[mi][ni][r] = 0.0f;

    auto ld32 = [](const __half* p) { return *(const uint32_t*)p; };

    auto compute_chunk = [&](const __half* st) {
#pragma unroll
        for (int ks = 0; ks < 2; ks++) {           // K=16 per mma
            const int u0 = woff[2 * ks], u1 = woff[2 * ks + 1];
            uint32_t a[4][4], b[4][2];
#pragma unroll
            for (int mi = 0; mi < 4; mi++) {
                const __half* p = st + arow[mi];
                a[mi][0] = ld32(p + u0);                     // row qr,   k
                a[mi][1] = ld32(p + 8 * ROW_H + u0);         // row qr+8, k
                a[mi][2] = ld32(p + u1);                     // row qr,   k+8
                a[mi][3] = ld32(p + 8 * ROW_H + u1);         // row qr+8, k+8
            }
#pragma unroll
            for (int ni = 0; ni < 4; ni++) {
                const __half* p = st + brow[ni];
                b[ni][0] = ld32(p + u0);
                b[ni][1] = ld32(p + u1);
            }
#pragma unroll
            for (int mi = 0; mi < 4; mi++)
#pragma unroll
                for (int ni = 0; ni < 4; ni++)
                    mma_f16(acc[mi][ni], a[mi], b[ni]);
        }
    };

    // ---------------- pipeline ----------------
    ldg_chunk(0);
    sts_chunk(stg[0]);
    ldg_chunk(1);
    __syncthreads();

#pragma unroll 1
    for (int c = 0; c < NCH; c++) {
        compute_chunk(stg[c & 1]);
        if (c < NCH - 1) {
            sts_chunk(stg[(c + 1) & 1]);           // regs hold chunk c+1
            if (c < NCH - 2) ldg_chunk(c + 2);     // hidden by compute(c+1)
        }
        __syncthreads();
    }

    // ---------------- epilogue: bias + relu, float2 stores ----------------
#pragma unroll
    for (int mi = 0; mi < 4; mi++) {
        const long r0 = m_base + mw * 64 + mi * 16 + qr;
#pragma unroll
        for (int ni = 0; ni < 4; ni++) {
            const int col = nw * 32 + ni * 8 + ql * 2;
            const float b0 = bsm[col], b1 = bsm[col + 1];
            float2 v0, v1;
            v0.x = fmaxf(acc[mi][ni][0] + b0, 0.0f);
            v0.y = fmaxf(acc[mi][ni][1] + b1, 0.0f);
            v1.x = fmaxf(acc[mi][ni][2] + b0, 0.0f);
            v1.y = fmaxf(acc[mi][ni][3] + b1, 0.0f);
            out2[r0 * 128 + (col >> 1)]       = v0;
            out2[(r0 + 8) * 128 + (col >> 1)] = v1;
        }
    }
}

extern "C" void kernel_launch(void* const* d_in, const int* in_sizes, int n_in,
                              void* d_out, int out_size) {
    const float* x = (const float*)d_in[0];   // [B, 256]
    const float* W = (const float*)d_in[1];   // [256, 256]
    const float* b = (const float*)d_in[2];   // [256]

    const int rows = in_sizes[0] / DIM;       // 131072
    const int grid = rows / TILE_M;           // 1024

    cudaFuncSetAttribute(gemm_bias_relu_f16,
                         cudaFuncAttributeMaxDynamicSharedMemorySize, SMEM_BYTES);
    gemm_bias_relu_f16<<<grid, THREADS, SMEM_BYTES>>>(
        (const float4*)x, (const float4*)W, b, (float2*)d_out);
}